// round 9
// baseline (speedup 1.0000x reference)
#include <cuda_runtime.h>

#define NG 128
#define FEAT 16
#define WIDTH 64
#define NUM_POS 3
#define IN_MLP 25          // FEAT + NUM_POS*3
#define HPITCH 28          // smem row pitch for h (112 B, 16B multiple)

// ---- packed f32x2 helpers (sm_10x) ----
__device__ __forceinline__ unsigned long long pack2(float a, float b) {
    unsigned long long r;
    asm("mov.b64 %0, {%1, %2};" : "=l"(r) : "f"(a), "f"(b));
    return r;
}
__device__ __forceinline__ void unpack2(unsigned long long v, float& a, float& b) {
    asm("mov.b64 {%0, %1}, %2;" : "=f"(a), "=f"(b) : "l"(v));
}
__device__ __forceinline__ unsigned long long fma2(unsigned long long a,
                                                   unsigned long long b,
                                                   unsigned long long c) {
    unsigned long long d;
    asm("fma.rn.f32x2 %0, %1, %2, %3;" : "=l"(d) : "l"(a), "l"(b), "l"(c));
    return d;
}

__device__ __forceinline__ void cubic_w(float t, float w[4]) {
    float t2 = t * t, t3 = t2 * t;
    w[0] = 0.5f * (-t3 + 2.0f * t2 - t);
    w[1] = 0.5f * (3.0f * t3 - 5.0f * t2 + 2.0f);
    w[2] = 0.5f * (-3.0f * t3 + 4.0f * t2 + t);
    w[3] = 0.5f * (t3 - t2);
}

// ============ fused gather + posenc + MLP: 16 lanes per point ============
// Gather (R1 shape): lane sub = (c, fg), c = z-tap, fg = feature float4 group.
// Then the same 16 lanes compute the MLP: lane sub covers hidden units
// {sub, sub+16, sub+32, sub+48} via two packed-f32x2 accumulators.
__global__ __launch_bounds__(256) void fused_kernel(
    const float* __restrict__ x,
    const float* __restrict__ grid,
    const float* __restrict__ w1,
    const float* __restrict__ b1,
    const float* __restrict__ w2,
    const float* __restrict__ b2,
    float* __restrict__ out,
    int npts)
{
    // 16B-aligned FIRST so float4 stores into s_h are legal.
    __shared__ __align__(16) float s_h[16][HPITCH];  // per-point input vectors
    // Packed weights: col = sub + 16*qq -> hidden pair (sub+32*qq, sub+32*qq+16)
    __shared__ unsigned long long s_wp[IN_MLP][32];
    __shared__ unsigned long long s_bp[32];
    __shared__ unsigned long long s_w2p[32];
    __shared__ float s_b2;

    for (int e = threadIdx.x; e < IN_MLP * 32; e += 256) {
        int i = e >> 5, col = e & 31;
        int sub = col & 15, qq = col >> 4;
        int j0 = sub + qq * 32;
        s_wp[i][col] = pack2(w1[j0 * IN_MLP + i], w1[(j0 + 16) * IN_MLP + i]);
    }
    if (threadIdx.x < 32) {
        int sub = threadIdx.x & 15, qq = threadIdx.x >> 4;
        int j0 = sub + qq * 32;
        s_bp[threadIdx.x]  = pack2(b1[j0], b1[j0 + 16]);
        s_w2p[threadIdx.x] = pack2(w2[j0], w2[j0 + 16]);
    }
    if (threadIdx.x == 0) s_b2 = b2[0];
    __syncthreads();

    int pslot = threadIdx.x >> 4;                 // 0..15 point slot in block
    int pt = blockIdx.x * 16 + pslot;
    bool live = (pt < npts);
    int ptc = live ? pt : (npts - 1);             // clamped (no early return)
    int sub = threadIdx.x & 15;
    int c   = sub >> 2;
    int fg  = sub & 3;

    // -------- gather phase (R1 shape) --------
    float ux = x[3 * ptc + 0] * 127.0f;
    float uy = x[3 * ptc + 1] * 127.0f;
    float uz = x[3 * ptc + 2] * 127.0f;
    float fx = floorf(ux), fy = floorf(uy), fz = floorf(uz);
    float tx = ux - fx, ty = uy - fy, tz = uz - fz;
    int ix0 = (int)fx, iy0 = (int)fy, iz0 = (int)fz;

    float wx[4], wy[4], wz[4];
    cubic_w(tx, wx);
    cubic_w(ty, wy);
    cubic_w(tz, wz);
    float wzc = wz[c];
    int zi = min(max(iz0 + c - 1, 0), NG - 1);

    float4 acc = make_float4(0.f, 0.f, 0.f, 0.f);
    #pragma unroll
    for (int a = 0; a < 4; a++) {
        int xi = min(max(ix0 + a - 1, 0), NG - 1);
        const float* gx = grid + (size_t)xi * (NG * NG * FEAT);
        float wxa = wx[a];
        #pragma unroll
        for (int b = 0; b < 4; b++) {
            int yi = min(max(iy0 + b - 1, 0), NG - 1);
            float w = wxa * wy[b] * wzc;
            const float4* gp =
                reinterpret_cast<const float4*>(gx + (yi * NG + zi) * FEAT) + fg;
            float4 v = __ldg(gp);
            acc.x += w * v.x;
            acc.y += w * v.y;
            acc.z += w * v.z;
            acc.w += w * v.w;
        }
    }

    const unsigned m = 0xFFFFFFFFu;
    acc.x += __shfl_xor_sync(m, acc.x, 4);
    acc.y += __shfl_xor_sync(m, acc.y, 4);
    acc.z += __shfl_xor_sync(m, acc.z, 4);
    acc.w += __shfl_xor_sync(m, acc.w, 4);
    acc.x += __shfl_xor_sync(m, acc.x, 8);
    acc.y += __shfl_xor_sync(m, acc.y, 8);
    acc.z += __shfl_xor_sync(m, acc.z, 8);
    acc.w += __shfl_xor_sync(m, acc.w, 8);

    if (c == 0)
        *reinterpret_cast<float4*>(&s_h[pslot][fg * 4]) = acc;

    // -------- positional encoding: lanes 0..8 compute one sin each --------
    if (sub < 9) {
        const float TWO_PI = 6.283185307179586f;
        int k = sub / 3, d = sub - 3 * k;
        float t = (d == 0) ? tx : (d == 1) ? ty : tz;
        s_h[pslot][FEAT + sub] = __sinf(TWO_PI * (float)(k + 1) * t);
    }
    __syncwarp();

    // -------- MLP phase: lane sub covers j in {sub, sub+16, sub+32, sub+48} --
    unsigned long long a0 = s_bp[sub];
    unsigned long long a1 = s_bp[16 + sub];
    #pragma unroll
    for (int i = 0; i < IN_MLP; i++) {
        float hv = s_h[pslot][i];                  // broadcast within 16-group
        unsigned long long hp = pack2(hv, hv);
        a0 = fma2(s_wp[i][sub],      hp, a0);
        a1 = fma2(s_wp[i][16 + sub], hp, a1);
    }
    float s0, s1, s2, s3;
    unpack2(a0, s0, s1);    // j = sub, sub+16
    unpack2(a1, s2, s3);    // j = sub+32, sub+48
    float g0 = s0 * __fdividef(1.0f, 1.0f + __expf(-s0));
    float g1 = s1 * __fdividef(1.0f, 1.0f + __expf(-s1));
    float g2 = s2 * __fdividef(1.0f, 1.0f + __expf(-s2));
    float g3 = s3 * __fdividef(1.0f, 1.0f + __expf(-s3));

    float w20, w21, w22, w23;
    unpack2(s_w2p[sub], w20, w21);
    unpack2(s_w2p[16 + sub], w22, w23);
    float local = w20 * g0 + w21 * g1 + w22 * g2 + w23 * g3;

    local += __shfl_xor_sync(m, local, 1);
    local += __shfl_xor_sync(m, local, 2);
    local += __shfl_xor_sync(m, local, 4);
    local += __shfl_xor_sync(m, local, 8);

    if (live && sub == 0)
        out[pt] = local + s_b2;
}

extern "C" void kernel_launch(void* const* d_in, const int* in_sizes, int n_in,
                              void* d_out, int out_size) {
    const float* x    = (const float*)d_in[0];
    const float* grid = (const float*)d_in[1];
    const float* w1   = (const float*)d_in[2];
    const float* b1   = (const float*)d_in[3];
    const float* w2   = (const float*)d_in[4];
    const float* b2   = (const float*)d_in[5];
    float* out = (float*)d_out;

    int npts = in_sizes[0] / 3;

    int blocks = (npts + 15) / 16;   // 16 points per 256-thread block
    fused_kernel<<<blocks, 256>>>(x, grid, w1, b1, w2, b2, out, npts);
}

// round 10
// speedup vs baseline: 1.1436x; 1.1436x over previous
#include <cuda_runtime.h>
#include <cuda_fp16.h>

#define NG 128
#define FEAT 16
#define WIDTH 64
#define NUM_POS 3
#define IN_MLP 25          // FEAT + NUM_POS*3
#define HPITCH 28          // smem row pitch for h (112 B, 16B multiple)
#define GRID_ELEMS (NG*NG*NG*FEAT)   // 33,554,432

// fp16 copy of the grid: 64 MB -> L2-resident (L2 = 126 MB).
__device__ __half g_grid_h[GRID_ELEMS];

// ---- packed f32x2 helpers (sm_10x) ----
__device__ __forceinline__ unsigned long long pack2(float a, float b) {
    unsigned long long r;
    asm("mov.b64 %0, {%1, %2};" : "=l"(r) : "f"(a), "f"(b));
    return r;
}
__device__ __forceinline__ void unpack2(unsigned long long v, float& a, float& b) {
    asm("mov.b64 {%0, %1}, %2;" : "=f"(a), "=f"(b) : "l"(v));
}
__device__ __forceinline__ unsigned long long fma2(unsigned long long a,
                                                   unsigned long long b,
                                                   unsigned long long c) {
    unsigned long long d;
    asm("fma.rn.f32x2 %0, %1, %2, %3;" : "=l"(d) : "l"(a), "l"(b), "l"(c));
    return d;
}
__device__ __forceinline__ unsigned h2u(__half2 h) {
    return *reinterpret_cast<unsigned*>(&h);
}

__device__ __forceinline__ void cubic_w(float t, float w[4]) {
    float t2 = t * t, t3 = t2 * t;
    w[0] = 0.5f * (-t3 + 2.0f * t2 - t);
    w[1] = 0.5f * (3.0f * t3 - 5.0f * t2 + 2.0f);
    w[2] = 0.5f * (-3.0f * t3 + 4.0f * t2 + t);
    w[3] = 0.5f * (t3 - t2);
}

// ============ grid fp32 -> fp16 convert (streaming, coalesced) ============
// 8 elements per thread: 2x float4 in, 1x uint4 (8 halfs) out.
__global__ __launch_bounds__(256) void convert_kernel(const float* __restrict__ grid) {
    int i = blockIdx.x * 256 + threadIdx.x;        // i indexes 8-element chunks
    const float4* src = reinterpret_cast<const float4*>(grid) + (size_t)i * 2;
    float4 a = __ldg(src);
    float4 b = __ldg(src + 1);
    uint4 o;
    o.x = h2u(__floats2half2_rn(a.x, a.y));
    o.y = h2u(__floats2half2_rn(a.z, a.w));
    o.z = h2u(__floats2half2_rn(b.x, b.y));
    o.w = h2u(__floats2half2_rn(b.z, b.w));
    reinterpret_cast<uint4*>(g_grid_h)[i] = o;
}

// ============ fused gather + posenc + MLP: 16 lanes per point ============
// Gather: lane sub = (c, fg), c = z-tap, fg = 4-feature group. Per (a,b) tap
// the 16 lanes read one contiguous 128B fp16 block (uint2 per lane).
// MLP: lane sub covers hidden units {sub, sub+16, sub+32, sub+48} via two
// packed-f32x2 accumulators.
__global__ __launch_bounds__(256) void fused_kernel(
    const float* __restrict__ x,
    const float* __restrict__ w1,
    const float* __restrict__ b1,
    const float* __restrict__ w2,
    const float* __restrict__ b2,
    float* __restrict__ out,
    int npts)
{
    __shared__ __align__(16) float s_h[16][HPITCH];  // per-point input vectors
    __shared__ unsigned long long s_wp[IN_MLP][32];
    __shared__ unsigned long long s_bp[32];
    __shared__ unsigned long long s_w2p[32];
    __shared__ float s_b2;

    for (int e = threadIdx.x; e < IN_MLP * 32; e += 256) {
        int i = e >> 5, col = e & 31;
        int sub = col & 15, qq = col >> 4;
        int j0 = sub + qq * 32;
        s_wp[i][col] = pack2(w1[j0 * IN_MLP + i], w1[(j0 + 16) * IN_MLP + i]);
    }
    if (threadIdx.x < 32) {
        int sub = threadIdx.x & 15, qq = threadIdx.x >> 4;
        int j0 = sub + qq * 32;
        s_bp[threadIdx.x]  = pack2(b1[j0], b1[j0 + 16]);
        s_w2p[threadIdx.x] = pack2(w2[j0], w2[j0 + 16]);
    }
    if (threadIdx.x == 0) s_b2 = b2[0];
    __syncthreads();

    int pslot = threadIdx.x >> 4;                 // 0..15 point slot in block
    int pt = blockIdx.x * 16 + pslot;
    bool live = (pt < npts);
    int ptc = live ? pt : (npts - 1);             // clamped (no early return)
    int sub = threadIdx.x & 15;
    int c   = sub >> 2;
    int fg  = sub & 3;

    // -------- gather phase (fp16 grid) --------
    float ux = x[3 * ptc + 0] * 127.0f;
    float uy = x[3 * ptc + 1] * 127.0f;
    float uz = x[3 * ptc + 2] * 127.0f;
    float fx = floorf(ux), fy = floorf(uy), fz = floorf(uz);
    float tx = ux - fx, ty = uy - fy, tz = uz - fz;
    int ix0 = (int)fx, iy0 = (int)fy, iz0 = (int)fz;

    float wx[4], wy[4], wz[4];
    cubic_w(tx, wx);
    cubic_w(ty, wy);
    cubic_w(tz, wz);
    float wzc = wz[c];
    int zi = min(max(iz0 + c - 1, 0), NG - 1);

    float4 acc = make_float4(0.f, 0.f, 0.f, 0.f);
    #pragma unroll
    for (int a = 0; a < 4; a++) {
        int xi = min(max(ix0 + a - 1, 0), NG - 1);
        const __half* gx = g_grid_h + (size_t)xi * (NG * NG * FEAT);
        float wxa = wx[a];
        #pragma unroll
        for (int b = 0; b < 4; b++) {
            int yi = min(max(iy0 + b - 1, 0), NG - 1);
            float w = wxa * wy[b] * wzc;
            const uint2* gp = reinterpret_cast<const uint2*>(
                gx + (yi * NG + zi) * FEAT + fg * 4);
            uint2 raw = __ldg(gp);
            float2 f0 = __half22float2(*reinterpret_cast<__half2*>(&raw.x));
            float2 f1 = __half22float2(*reinterpret_cast<__half2*>(&raw.y));
            acc.x += w * f0.x;
            acc.y += w * f0.y;
            acc.z += w * f1.x;
            acc.w += w * f1.y;
        }
    }

    const unsigned m = 0xFFFFFFFFu;
    acc.x += __shfl_xor_sync(m, acc.x, 4);
    acc.y += __shfl_xor_sync(m, acc.y, 4);
    acc.z += __shfl_xor_sync(m, acc.z, 4);
    acc.w += __shfl_xor_sync(m, acc.w, 4);
    acc.x += __shfl_xor_sync(m, acc.x, 8);
    acc.y += __shfl_xor_sync(m, acc.y, 8);
    acc.z += __shfl_xor_sync(m, acc.z, 8);
    acc.w += __shfl_xor_sync(m, acc.w, 8);

    if (c == 0)
        *reinterpret_cast<float4*>(&s_h[pslot][fg * 4]) = acc;

    // -------- positional encoding: lanes 0..8 compute one sin each --------
    if (sub < 9) {
        const float TWO_PI = 6.283185307179586f;
        int k = sub / 3, d = sub - 3 * k;
        float t = (d == 0) ? tx : (d == 1) ? ty : tz;
        s_h[pslot][FEAT + sub] = __sinf(TWO_PI * (float)(k + 1) * t);
    }
    __syncwarp();

    // -------- MLP phase: lane sub covers j in {sub, sub+16, sub+32, sub+48} --
    unsigned long long a0 = s_bp[sub];
    unsigned long long a1 = s_bp[16 + sub];
    #pragma unroll
    for (int i = 0; i < IN_MLP; i++) {
        float hv = s_h[pslot][i];                  // broadcast within 16-group
        unsigned long long hp = pack2(hv, hv);
        a0 = fma2(s_wp[i][sub],      hp, a0);
        a1 = fma2(s_wp[i][16 + sub], hp, a1);
    }
    float s0, s1, s2, s3;
    unpack2(a0, s0, s1);    // j = sub, sub+16
    unpack2(a1, s2, s3);    // j = sub+32, sub+48
    float g0 = s0 * __fdividef(1.0f, 1.0f + __expf(-s0));
    float g1 = s1 * __fdividef(1.0f, 1.0f + __expf(-s1));
    float g2 = s2 * __fdividef(1.0f, 1.0f + __expf(-s2));
    float g3 = s3 * __fdividef(1.0f, 1.0f + __expf(-s3));

    float w20, w21, w22, w23;
    unpack2(s_w2p[sub], w20, w21);
    unpack2(s_w2p[16 + sub], w22, w23);
    float local = w20 * g0 + w21 * g1 + w22 * g2 + w23 * g3;

    local += __shfl_xor_sync(m, local, 1);
    local += __shfl_xor_sync(m, local, 2);
    local += __shfl_xor_sync(m, local, 4);
    local += __shfl_xor_sync(m, local, 8);

    if (live && sub == 0)
        out[pt] = local + s_b2;
}

extern "C" void kernel_launch(void* const* d_in, const int* in_sizes, int n_in,
                              void* d_out, int out_size) {
    const float* x    = (const float*)d_in[0];
    const float* grid = (const float*)d_in[1];
    const float* w1   = (const float*)d_in[2];
    const float* b1   = (const float*)d_in[3];
    const float* w2   = (const float*)d_in[4];
    const float* b2   = (const float*)d_in[5];
    float* out = (float*)d_out;

    int npts = in_sizes[0] / 3;

    convert_kernel<<<GRID_ELEMS / 8 / 256, 256>>>(grid);  // 16384 blocks

    int blocks = (npts + 15) / 16;   // 16 points per 256-thread block
    fused_kernel<<<blocks, 256>>>(x, w1, b1, w2, b2, out, npts);
}

// round 11
// speedup vs baseline: 1.1845x; 1.0358x over previous
#include <cuda_runtime.h>
#include <cuda_fp16.h>

#define NG 128
#define FEAT 16
#define WIDTH 64
#define NUM_POS 3
#define IN_MLP 25          // FEAT + NUM_POS*3
#define GRID_ELEMS (NG*NG*NG*FEAT)   // 33,554,432

// fp16 copy of the grid: 64 MB -> L2-resident (L2 = 126 MB).
__device__ __half g_grid_h[GRID_ELEMS];

// ---- packed f32x2 helpers (sm_10x) ----
__device__ __forceinline__ unsigned long long pack2(float a, float b) {
    unsigned long long r;
    asm("mov.b64 %0, {%1, %2};" : "=l"(r) : "f"(a), "f"(b));
    return r;
}
__device__ __forceinline__ void unpack2(unsigned long long v, float& a, float& b) {
    asm("mov.b64 {%0, %1}, %2;" : "=f"(a), "=f"(b) : "l"(v));
}
__device__ __forceinline__ unsigned long long fma2(unsigned long long a,
                                                   unsigned long long b,
                                                   unsigned long long c) {
    unsigned long long d;
    asm("fma.rn.f32x2 %0, %1, %2, %3;" : "=l"(d) : "l"(a), "l"(b), "l"(c));
    return d;
}
__device__ __forceinline__ unsigned h2u(__half2 h) {
    return *reinterpret_cast<unsigned*>(&h);
}
__device__ __forceinline__ unsigned fbits(float f) {
    return __float_as_uint(f);
}

__device__ __forceinline__ void cubic_w(float t, float w[4]) {
    float t2 = t * t, t3 = t2 * t;
    w[0] = 0.5f * (-t3 + 2.0f * t2 - t);
    w[1] = 0.5f * (3.0f * t3 - 5.0f * t2 + 2.0f);
    w[2] = 0.5f * (-3.0f * t3 + 4.0f * t2 + t);
    w[3] = 0.5f * (t3 - t2);
}

// ============ grid fp32 -> fp16 convert (streaming, coalesced) ============
__global__ __launch_bounds__(256) void convert_kernel(const float* __restrict__ grid) {
    int i = blockIdx.x * 256 + threadIdx.x;        // i indexes 8-element chunks
    const float4* src = reinterpret_cast<const float4*>(grid) + (size_t)i * 2;
    float4 a = __ldg(src);
    float4 b = __ldg(src + 1);
    uint4 o;
    o.x = h2u(__floats2half2_rn(a.x, a.y));
    o.y = h2u(__floats2half2_rn(a.z, a.w));
    o.z = h2u(__floats2half2_rn(b.x, b.y));
    o.w = h2u(__floats2half2_rn(b.z, b.w));
    reinterpret_cast<uint4*>(g_grid_h)[i] = o;
}

// ============ fused gather + posenc + MLP: 8 lanes per point, 4 pts/warp ====
// Gather: lane sub = (c, fh): c = z-tap (bits 1-2), fh = 8-feature half (bit 0).
// Per (a,b) tap each lane loads one uint4 (8 fp16) -> 8 lanes cover the
// contiguous 128B 4z x 16f block. c-reduction via shfl_xor(2),(4).
// MLP: h broadcast via shuffles (no smem h traffic); each lane computes 8
// hidden units via 4 packed-f32x2 accumulators; weight LDS dedups across the
// warp's 4 point groups (12.5 wf/pt).
__global__ __launch_bounds__(256) void fused_kernel(
    const float* __restrict__ x,
    const float* __restrict__ w1,
    const float* __restrict__ b1,
    const float* __restrict__ w2,
    const float* __restrict__ b2,
    float* __restrict__ out,
    int npts)
{
    // s_wA[i][sub] = w1 col i for units (sub, sub+8, sub+16, sub+24)
    // s_wB[i][sub] = w1 col i for units (sub+32, sub+40, sub+48, sub+56)
    __shared__ uint4 s_wA[IN_MLP][8];
    __shared__ uint4 s_wB[IN_MLP][8];
    __shared__ uint4 s_bA[8], s_bB[8];
    __shared__ uint4 s_w2A[8], s_w2B[8];
    __shared__ float s_b2;

    for (int e = threadIdx.x; e < IN_MLP * 8; e += 256) {
        int i = e >> 3, sub = e & 7;
        s_wA[i][sub] = make_uint4(fbits(w1[(sub +  0) * IN_MLP + i]),
                                  fbits(w1[(sub +  8) * IN_MLP + i]),
                                  fbits(w1[(sub + 16) * IN_MLP + i]),
                                  fbits(w1[(sub + 24) * IN_MLP + i]));
        s_wB[i][sub] = make_uint4(fbits(w1[(sub + 32) * IN_MLP + i]),
                                  fbits(w1[(sub + 40) * IN_MLP + i]),
                                  fbits(w1[(sub + 48) * IN_MLP + i]),
                                  fbits(w1[(sub + 56) * IN_MLP + i]));
    }
    if (threadIdx.x < 8) {
        int sub = threadIdx.x;
        s_bA[sub]  = make_uint4(fbits(b1[sub]), fbits(b1[sub + 8]),
                                fbits(b1[sub + 16]), fbits(b1[sub + 24]));
        s_bB[sub]  = make_uint4(fbits(b1[sub + 32]), fbits(b1[sub + 40]),
                                fbits(b1[sub + 48]), fbits(b1[sub + 56]));
        s_w2A[sub] = make_uint4(fbits(w2[sub]), fbits(w2[sub + 8]),
                                fbits(w2[sub + 16]), fbits(w2[sub + 24]));
        s_w2B[sub] = make_uint4(fbits(w2[sub + 32]), fbits(w2[sub + 40]),
                                fbits(w2[sub + 48]), fbits(w2[sub + 56]));
    }
    if (threadIdx.x == 0) s_b2 = b2[0];
    __syncthreads();

    int warpId = threadIdx.x >> 5;
    int lane   = threadIdx.x & 31;
    int g      = lane >> 3;          // point group 0..3
    int sub    = lane & 7;
    int c      = sub >> 1;           // z-tap 0..3
    int fh     = sub & 1;            // feature half 0..1
    int base_lane = lane & 24;       // g*8

    int pt = blockIdx.x * 32 + warpId * 4 + g;
    bool live = (pt < npts);
    int ptc = live ? pt : (npts - 1);

    // -------- gather (fp16 grid) --------
    float ux = __ldg(&x[3 * ptc + 0]) * 127.0f;
    float uy = __ldg(&x[3 * ptc + 1]) * 127.0f;
    float uz = __ldg(&x[3 * ptc + 2]) * 127.0f;
    float fx = floorf(ux), fy = floorf(uy), fz = floorf(uz);
    float tx = ux - fx, ty = uy - fy, tz = uz - fz;
    int ix0 = (int)fx, iy0 = (int)fy, iz0 = (int)fz;

    float wx[4], wy[4], wz[4];
    cubic_w(tx, wx);
    cubic_w(ty, wy);
    cubic_w(tz, wz);
    float wzc = wz[c];
    int zi = min(max(iz0 + c - 1, 0), NG - 1);
    int foff = fh * 8;

    float4 accA = make_float4(0.f, 0.f, 0.f, 0.f);   // feats fh*8 + 0..3
    float4 accB = make_float4(0.f, 0.f, 0.f, 0.f);   // feats fh*8 + 4..7
    #pragma unroll
    for (int a = 0; a < 4; a++) {
        int xi = min(max(ix0 + a - 1, 0), NG - 1);
        const __half* gx = g_grid_h + (size_t)xi * (NG * NG * FEAT);
        float wxa = wx[a];
        #pragma unroll
        for (int b = 0; b < 4; b++) {
            int yi = min(max(iy0 + b - 1, 0), NG - 1);
            float w = wxa * wy[b] * wzc;
            const uint4* gp = reinterpret_cast<const uint4*>(
                gx + (yi * NG + zi) * FEAT + foff);
            uint4 raw = __ldg(gp);
            float2 f0 = __half22float2(*reinterpret_cast<__half2*>(&raw.x));
            float2 f1 = __half22float2(*reinterpret_cast<__half2*>(&raw.y));
            float2 f2 = __half22float2(*reinterpret_cast<__half2*>(&raw.z));
            float2 f3 = __half22float2(*reinterpret_cast<__half2*>(&raw.w));
            accA.x += w * f0.x;  accA.y += w * f0.y;
            accA.z += w * f1.x;  accA.w += w * f1.y;
            accB.x += w * f2.x;  accB.y += w * f2.y;
            accB.z += w * f3.x;  accB.w += w * f3.y;
        }
    }

    // Reduce over c (lane bits 1 and 2).
    const unsigned m = 0xFFFFFFFFu;
    accA.x += __shfl_xor_sync(m, accA.x, 2);  accA.x += __shfl_xor_sync(m, accA.x, 4);
    accA.y += __shfl_xor_sync(m, accA.y, 2);  accA.y += __shfl_xor_sync(m, accA.y, 4);
    accA.z += __shfl_xor_sync(m, accA.z, 2);  accA.z += __shfl_xor_sync(m, accA.z, 4);
    accA.w += __shfl_xor_sync(m, accA.w, 2);  accA.w += __shfl_xor_sync(m, accA.w, 4);
    accB.x += __shfl_xor_sync(m, accB.x, 2);  accB.x += __shfl_xor_sync(m, accB.x, 4);
    accB.y += __shfl_xor_sync(m, accB.y, 2);  accB.y += __shfl_xor_sync(m, accB.y, 4);
    accB.z += __shfl_xor_sync(m, accB.z, 2);  accB.z += __shfl_xor_sync(m, accB.z, 4);
    accB.w += __shfl_xor_sync(m, accB.w, 2);  accB.w += __shfl_xor_sync(m, accB.w, 4);
    // Now lane (g, fh=0) holds feats 0..7; (g, fh=1) holds feats 8..15.

    // -------- positional encoding in registers --------
    const float TWO_PI = 6.283185307179586f;
    float t3[3] = {tx, ty, tz};
    int pk = sub / 3;                 // 0..2 for sub 0..7
    int pd = sub - 3 * pk;
    float ps  = __sinf(TWO_PI * (float)(pk + 1) * t3[pd]);  // sin index 'sub' (0..7)
    float ps8 = __sinf(TWO_PI * 3.0f * tz);                 // sin index 8 (local)

    // -------- MLP: h via shuffles, weights via dedup'd LDS.128 --------
    ulonglong2 bA = *reinterpret_cast<const ulonglong2*>(&s_bA[sub]);
    ulonglong2 bB = *reinterpret_cast<const ulonglong2*>(&s_bB[sub]);
    unsigned long long acc0 = bA.x;   // units (sub,    sub+8)
    unsigned long long acc1 = bA.y;   // units (sub+16, sub+24)
    unsigned long long acc2 = bB.x;   // units (sub+32, sub+40)
    unsigned long long acc3 = bB.y;   // units (sub+48, sub+56)

    #pragma unroll
    for (int i = 0; i < IN_MLP; i++) {
        float hv;
        if (i < 16) {
            float v = ((i >> 2) & 1)
                ? ((i & 3) == 0 ? accB.x : (i & 3) == 1 ? accB.y
                                 : (i & 3) == 2 ? accB.z : accB.w)
                : ((i & 3) == 0 ? accA.x : (i & 3) == 1 ? accA.y
                                 : (i & 3) == 2 ? accA.z : accA.w);
            hv = __shfl_sync(m, v, base_lane + (i >> 3));
        } else if (i < 24) {
            hv = __shfl_sync(m, ps, base_lane + (i - 16));
        } else {
            hv = ps8;
        }
        unsigned long long hp = pack2(hv, hv);
        ulonglong2 wa = *reinterpret_cast<const ulonglong2*>(&s_wA[i][sub]);
        ulonglong2 wb = *reinterpret_cast<const ulonglong2*>(&s_wB[i][sub]);
        acc0 = fma2(wa.x, hp, acc0);
        acc1 = fma2(wa.y, hp, acc1);
        acc2 = fma2(wb.x, hp, acc2);
        acc3 = fma2(wb.y, hp, acc3);
    }

    float s0, s1, s2, s3, s4, s5, s6, s7;
    unpack2(acc0, s0, s1);
    unpack2(acc1, s2, s3);
    unpack2(acc2, s4, s5);
    unpack2(acc3, s6, s7);
    float q0 = s0 * __fdividef(1.0f, 1.0f + __expf(-s0));
    float q1 = s1 * __fdividef(1.0f, 1.0f + __expf(-s1));
    float q2 = s2 * __fdividef(1.0f, 1.0f + __expf(-s2));
    float q3 = s3 * __fdividef(1.0f, 1.0f + __expf(-s3));
    float q4 = s4 * __fdividef(1.0f, 1.0f + __expf(-s4));
    float q5 = s5 * __fdividef(1.0f, 1.0f + __expf(-s5));
    float q6 = s6 * __fdividef(1.0f, 1.0f + __expf(-s6));
    float q7 = s7 * __fdividef(1.0f, 1.0f + __expf(-s7));

    uint4 w2a = s_w2A[sub];
    uint4 w2b = s_w2B[sub];
    float local = __uint_as_float(w2a.x) * q0 + __uint_as_float(w2a.y) * q1
                + __uint_as_float(w2a.z) * q2 + __uint_as_float(w2a.w) * q3
                + __uint_as_float(w2b.x) * q4 + __uint_as_float(w2b.y) * q5
                + __uint_as_float(w2b.z) * q6 + __uint_as_float(w2b.w) * q7;

    local += __shfl_xor_sync(m, local, 1);
    local += __shfl_xor_sync(m, local, 2);
    local += __shfl_xor_sync(m, local, 4);

    if (live && sub == 0)
        out[pt] = local + s_b2;
}

extern "C" void kernel_launch(void* const* d_in, const int* in_sizes, int n_in,
                              void* d_out, int out_size) {
    const float* x    = (const float*)d_in[0];
    const float* grid = (const float*)d_in[1];
    const float* w1   = (const float*)d_in[2];
    const float* b1   = (const float*)d_in[3];
    const float* w2   = (const float*)d_in[4];
    const float* b2   = (const float*)d_in[5];
    float* out = (float*)d_out;

    int npts = in_sizes[0] / 3;

    convert_kernel<<<GRID_ELEMS / 8 / 256, 256>>>(grid);  // 16384 blocks

    int blocks = (npts + 31) / 32;   // 32 points per 256-thread block
    fused_kernel<<<blocks, 256>>>(x, w1, b1, w2, b2, out, npts);
}

// round 12
// speedup vs baseline: 1.5714x; 1.3266x over previous
#include <cuda_runtime.h>
#include <cuda_fp16.h>

#define NG 128
#define FEAT 16
#define WIDTH 64
#define NUM_POS 3
#define IN_MLP 25          // FEAT + NUM_POS*3
#define GRID_ELEMS (NG*NG*NG*FEAT)   // 33,554,432

// fp16 copy of the grid: 64 MB -> L2-resident (L2 = 126 MB).
__device__ __half g_grid_h[GRID_ELEMS];

// ---- packed f32x2 helpers (sm_10x) ----
__device__ __forceinline__ unsigned long long pack2(float a, float b) {
    unsigned long long r;
    asm("mov.b64 %0, {%1, %2};" : "=l"(r) : "f"(a), "f"(b));
    return r;
}
__device__ __forceinline__ void unpack2(unsigned long long v, float& a, float& b) {
    asm("mov.b64 {%0, %1}, %2;" : "=f"(a), "=f"(b) : "l"(v));
}
__device__ __forceinline__ unsigned long long fma2(unsigned long long a,
                                                   unsigned long long b,
                                                   unsigned long long c) {
    unsigned long long d;
    asm("fma.rn.f32x2 %0, %1, %2, %3;" : "=l"(d) : "l"(a), "l"(b), "l"(c));
    return d;
}
__device__ __forceinline__ unsigned h2u(__half2 h) {
    return *reinterpret_cast<unsigned*>(&h);
}
__device__ __forceinline__ unsigned fbits(float f) {
    return __float_as_uint(f);
}
__device__ __forceinline__ float redc(float v) {   // reduce over lane bits 1,2
    v += __shfl_xor_sync(0xFFFFFFFFu, v, 2);
    v += __shfl_xor_sync(0xFFFFFFFFu, v, 4);
    return v;
}

__device__ __forceinline__ void cubic_w(float t, float w[4]) {
    float t2 = t * t, t3 = t2 * t;
    w[0] = 0.5f * (-t3 + 2.0f * t2 - t);
    w[1] = 0.5f * (3.0f * t3 - 5.0f * t2 + 2.0f);
    w[2] = 0.5f * (-3.0f * t3 + 4.0f * t2 + t);
    w[3] = 0.5f * (t3 - t2);
}

// ============ grid fp32 -> fp16 convert (streaming, coalesced) ============
__global__ __launch_bounds__(256) void convert_kernel(const float* __restrict__ grid) {
    int i = blockIdx.x * 256 + threadIdx.x;        // i indexes 8-element chunks
    const float4* src = reinterpret_cast<const float4*>(grid) + (size_t)i * 2;
    float4 a = __ldg(src);
    float4 b = __ldg(src + 1);
    uint4 o;
    o.x = h2u(__floats2half2_rn(a.x, a.y));
    o.y = h2u(__floats2half2_rn(a.z, a.w));
    o.z = h2u(__floats2half2_rn(b.x, b.y));
    o.w = h2u(__floats2half2_rn(b.z, b.w));
    reinterpret_cast<uint4*>(g_grid_h)[i] = o;
}

// ============ fused: 8 lanes per point-pair, 8 points per warp ============
// Gather: lane sub = (c, fh); each 8-lane group gathers TWO points (p0, p1)
// sequentially. MLP: per input i, ONE weight LDS pair serves all 8 points of
// the warp (h broadcast via 2 shuffles) -> weight wavefronts halve per point.
__global__ __launch_bounds__(256) void fused_kernel(
    const float* __restrict__ x,
    const float* __restrict__ w1,
    const float* __restrict__ b1,
    const float* __restrict__ w2,
    const float* __restrict__ b2,
    float* __restrict__ out,
    int npts)
{
    // s_wA[i][sub] = w1 col i for units (sub, sub+8, sub+16, sub+24)
    // s_wB[i][sub] = w1 col i for units (sub+32, sub+40, sub+48, sub+56)
    __shared__ uint4 s_wA[IN_MLP][8];
    __shared__ uint4 s_wB[IN_MLP][8];
    __shared__ uint4 s_bA[8], s_bB[8];
    __shared__ uint4 s_w2A[8], s_w2B[8];
    __shared__ float s_b2;

    for (int e = threadIdx.x; e < IN_MLP * 8; e += 256) {
        int i = e >> 3, sub = e & 7;
        s_wA[i][sub] = make_uint4(fbits(w1[(sub +  0) * IN_MLP + i]),
                                  fbits(w1[(sub +  8) * IN_MLP + i]),
                                  fbits(w1[(sub + 16) * IN_MLP + i]),
                                  fbits(w1[(sub + 24) * IN_MLP + i]));
        s_wB[i][sub] = make_uint4(fbits(w1[(sub + 32) * IN_MLP + i]),
                                  fbits(w1[(sub + 40) * IN_MLP + i]),
                                  fbits(w1[(sub + 48) * IN_MLP + i]),
                                  fbits(w1[(sub + 56) * IN_MLP + i]));
    }
    if (threadIdx.x < 8) {
        int sub = threadIdx.x;
        s_bA[sub]  = make_uint4(fbits(b1[sub]), fbits(b1[sub + 8]),
                                fbits(b1[sub + 16]), fbits(b1[sub + 24]));
        s_bB[sub]  = make_uint4(fbits(b1[sub + 32]), fbits(b1[sub + 40]),
                                fbits(b1[sub + 48]), fbits(b1[sub + 56]));
        s_w2A[sub] = make_uint4(fbits(w2[sub]), fbits(w2[sub + 8]),
                                fbits(w2[sub + 16]), fbits(w2[sub + 24]));
        s_w2B[sub] = make_uint4(fbits(w2[sub + 32]), fbits(w2[sub + 40]),
                                fbits(w2[sub + 48]), fbits(w2[sub + 56]));
    }
    if (threadIdx.x == 0) s_b2 = b2[0];
    __syncthreads();

    int warpId = threadIdx.x >> 5;
    int lane   = threadIdx.x & 31;
    int g      = lane >> 3;          // point group 0..3
    int sub    = lane & 7;
    int c      = sub >> 1;           // z-tap 0..3
    int fh     = sub & 1;            // feature half 0..1
    int base_lane = lane & 24;       // g*8
    int foff   = fh * 8;

    int p0 = blockIdx.x * 64 + warpId * 8 + g * 2;   // this group's two points
    int p1 = p0 + 1;
    bool live0 = (p0 < npts), live1 = (p1 < npts);
    int pc[2];
    pc[0] = live0 ? p0 : npts - 1;
    pc[1] = live1 ? p1 : npts - 1;

    const unsigned m = 0xFFFFFFFFu;
    float4 accA[2], accB[2];
    float ps[2], ps8[2];

    int pk = sub / 3;                 // posenc decomposition of sub (0..7)
    int pd = sub - 3 * pk;
    const float TWO_PI = 6.283185307179586f;

    #pragma unroll
    for (int p = 0; p < 2; p++) {
        int ptc = pc[p];
        float ux = __ldg(&x[3 * ptc + 0]) * 127.0f;
        float uy = __ldg(&x[3 * ptc + 1]) * 127.0f;
        float uz = __ldg(&x[3 * ptc + 2]) * 127.0f;
        float fx = floorf(ux), fy = floorf(uy), fz = floorf(uz);
        float tx = ux - fx, ty = uy - fy, tz = uz - fz;
        int ix0 = (int)fx, iy0 = (int)fy, iz0 = (int)fz;

        float wx[4], wy[4], wz[4];
        cubic_w(tx, wx);
        cubic_w(ty, wy);
        cubic_w(tz, wz);
        float wzc = wz[c];
        int zi = min(max(iz0 + c - 1, 0), NG - 1);

        float4 aA = make_float4(0.f, 0.f, 0.f, 0.f);
        float4 aB = make_float4(0.f, 0.f, 0.f, 0.f);
        #pragma unroll
        for (int a = 0; a < 4; a++) {
            int xi = min(max(ix0 + a - 1, 0), NG - 1);
            const __half* gx = g_grid_h + (size_t)xi * (NG * NG * FEAT);
            float wxa = wx[a];
            #pragma unroll
            for (int b = 0; b < 4; b++) {
                int yi = min(max(iy0 + b - 1, 0), NG - 1);
                float w = wxa * wy[b] * wzc;
                const uint4* gp = reinterpret_cast<const uint4*>(
                    gx + (yi * NG + zi) * FEAT + foff);
                uint4 raw = __ldg(gp);
                float2 f0 = __half22float2(*reinterpret_cast<__half2*>(&raw.x));
                float2 f1 = __half22float2(*reinterpret_cast<__half2*>(&raw.y));
                float2 f2 = __half22float2(*reinterpret_cast<__half2*>(&raw.z));
                float2 f3 = __half22float2(*reinterpret_cast<__half2*>(&raw.w));
                aA.x += w * f0.x;  aA.y += w * f0.y;
                aA.z += w * f1.x;  aA.w += w * f1.y;
                aB.x += w * f2.x;  aB.y += w * f2.y;
                aB.z += w * f3.x;  aB.w += w * f3.y;
            }
        }
        // reduce over c (lane bits 1,2)
        aA.x = redc(aA.x);  aA.y = redc(aA.y);  aA.z = redc(aA.z);  aA.w = redc(aA.w);
        aB.x = redc(aB.x);  aB.y = redc(aB.y);  aB.z = redc(aB.z);  aB.w = redc(aB.w);
        accA[p] = aA;
        accB[p] = aB;

        float t3v = (pd == 0) ? tx : (pd == 1) ? ty : tz;
        ps[p]  = __sinf(TWO_PI * (float)(pk + 1) * t3v);   // sin index 'sub'
        ps8[p] = __sinf(TWO_PI * 3.0f * tz);               // sin index 8
    }
    // lane (g, fh=0) holds feats 0..7 of both points; fh=1 holds 8..15.

    // -------- MLP: one weight LDS pair per i serves all 8 warp points --------
    ulonglong2 bA = *reinterpret_cast<const ulonglong2*>(&s_bA[sub]);
    ulonglong2 bB = *reinterpret_cast<const ulonglong2*>(&s_bB[sub]);
    unsigned long long q0[2], q1[2], q2[2], q3[2];
    #pragma unroll
    for (int p = 0; p < 2; p++) {
        q0[p] = bA.x;  q1[p] = bA.y;  q2[p] = bB.x;  q3[p] = bB.y;
    }

    #pragma unroll
    for (int i = 0; i < IN_MLP; i++) {
        ulonglong2 wa = *reinterpret_cast<const ulonglong2*>(&s_wA[i][sub]);
        ulonglong2 wb = *reinterpret_cast<const ulonglong2*>(&s_wB[i][sub]);
        #pragma unroll
        for (int p = 0; p < 2; p++) {
            float hv;
            if (i < 16) {
                float v = ((i >> 2) & 1)
                    ? ((i & 3) == 0 ? accB[p].x : (i & 3) == 1 ? accB[p].y
                                     : (i & 3) == 2 ? accB[p].z : accB[p].w)
                    : ((i & 3) == 0 ? accA[p].x : (i & 3) == 1 ? accA[p].y
                                     : (i & 3) == 2 ? accA[p].z : accA[p].w);
                hv = __shfl_sync(m, v, base_lane + (i >> 3));
            } else if (i < 24) {
                hv = __shfl_sync(m, ps[p], base_lane + (i - 16));
            } else {
                hv = ps8[p];
            }
            unsigned long long hp = pack2(hv, hv);
            q0[p] = fma2(wa.x, hp, q0[p]);
            q1[p] = fma2(wa.y, hp, q1[p]);
            q2[p] = fma2(wb.x, hp, q2[p]);
            q3[p] = fma2(wb.y, hp, q3[p]);
        }
    }

    uint4 w2a = s_w2A[sub];
    uint4 w2b = s_w2B[sub];
    #pragma unroll
    for (int p = 0; p < 2; p++) {
        float s0, s1, s2, s3, s4, s5, s6, s7;
        unpack2(q0[p], s0, s1);
        unpack2(q1[p], s2, s3);
        unpack2(q2[p], s4, s5);
        unpack2(q3[p], s6, s7);
        float r0 = s0 * __fdividef(1.0f, 1.0f + __expf(-s0));
        float r1 = s1 * __fdividef(1.0f, 1.0f + __expf(-s1));
        float r2 = s2 * __fdividef(1.0f, 1.0f + __expf(-s2));
        float r3 = s3 * __fdividef(1.0f, 1.0f + __expf(-s3));
        float r4 = s4 * __fdividef(1.0f, 1.0f + __expf(-s4));
        float r5 = s5 * __fdividef(1.0f, 1.0f + __expf(-s5));
        float r6 = s6 * __fdividef(1.0f, 1.0f + __expf(-s6));
        float r7 = s7 * __fdividef(1.0f, 1.0f + __expf(-s7));

        float local = __uint_as_float(w2a.x) * r0 + __uint_as_float(w2a.y) * r1
                    + __uint_as_float(w2a.z) * r2 + __uint_as_float(w2a.w) * r3
                    + __uint_as_float(w2b.x) * r4 + __uint_as_float(w2b.y) * r5
                    + __uint_as_float(w2b.z) * r6 + __uint_as_float(w2b.w) * r7;

        local += __shfl_xor_sync(m, local, 1);
        local += __shfl_xor_sync(m, local, 2);
        local += __shfl_xor_sync(m, local, 4);

        bool live = p ? live1 : live0;
        int  pw   = p ? p1 : p0;
        if (live && sub == 0)
            out[pw] = local + s_b2;
    }
}

extern "C" void kernel_launch(void* const* d_in, const int* in_sizes, int n_in,
                              void* d_out, int out_size) {
    const float* x    = (const float*)d_in[0];
    const float* grid = (const float*)d_in[1];
    const float* w1   = (const float*)d_in[2];
    const float* b1   = (const float*)d_in[3];
    const float* w2   = (const float*)d_in[4];
    const float* b2   = (const float*)d_in[5];
    float* out = (float*)d_out;

    int npts = in_sizes[0] / 3;

    convert_kernel<<<GRID_ELEMS / 8 / 256, 256>>>(grid);  // 16384 blocks

    int blocks = (npts + 63) / 64;   // 64 points per 256-thread block
    fused_kernel<<<blocks, 256>>>(x, w1, b1, w2, b2, out, npts);
}